// round 14
// baseline (speedup 1.0000x reference)
#include <cuda_runtime.h>

// Problem constants (fixed by setup_inputs)
#define T_LEN 8192
#define H_HEADS 16
#define B_BATCH 2
#define P_DIM 64
#define N_DIM 64
#define BH (B_BATCH * H_HEADS)   // 32

#define KS 32                    // timesteps per item (one slice)
#define NSLICE (T_LEN / KS)      // 256
#define SPLIT 4                  // item-split blocks per quadrant group
#define QP 32                    // quadrant p-size
#define QN 32                    // quadrant n-size
#define NGROUP (BH * 4)          // 128 quadrant groups
// exp(-12) ~ 6e-6: dropped tail perturbs result ~3e-5 relative; gate is 1e-3.
#define THRESH 12.0f

// Scratch (allocation-free rule: device globals; zero-init at module load)
__device__ float        g_part[NGROUP * SPLIT * QP * QN];  // per-block partials (2 MB)
__device__ unsigned int g_cnt[NGROUP];                     // arrival tickets

// ---- packed fp32x2 helpers (sm_100+; PTX-only) ----
__device__ __forceinline__ unsigned long long fma2(unsigned long long a,
                                                   unsigned long long b,
                                                   unsigned long long c) {
    unsigned long long d;
    asm("fma.rn.f32x2 %0, %1, %2, %3;" : "=l"(d) : "l"(a), "l"(b), "l"(c));
    return d;
}
__device__ __forceinline__ unsigned long long pack2(float x) {
    unsigned long long d;
    asm("mov.b64 %0, {%1, %1};" : "=l"(d) : "f"(x));
    return d;
}

// ---------------------------------------------------------------------------
// Single fused kernel. Grid = NGROUP*SPLIT = 512 blocks, 128 threads.
// Group g = (bh, quadrant); its SPLIT blocks round-robin the 32-t items
// (newest slice first), each carrying its own incremental tail. Partials go
// to private scratch slots; the last-arriving block of the group combines
// them (fixed slot order => deterministic) and plain-stores the output.
// No memset, no output atomics, one graph node.
// ---------------------------------------------------------------------------
__global__ void __launch_bounds__(128)
state_kernel(const float* __restrict__ X, const float* __restrict__ Bm,
             const float* __restrict__ A, float* __restrict__ out) {
    int blk = blockIdx.x;
    int g = blk >> 2;            // group: bh*4 + quad
    int s0 = blk & 3;            // item-split index
    int bh = g >> 2;
    int quad = g & 3;
    int ph = (quad >> 1) * QP;
    int nb = (quad & 1) * QN;
    int tid = threadIdx.x;
    int lane = tid & 31;
    int b = bh / H_HEADS, hh = bh % H_HEADS;

    __shared__ float sX[KS][QP];
    __shared__ float sB[KS][QN];
    __shared__ unsigned s_tick;

    const float* Ab = A + (size_t)b * T_LEN * H_HEADS + hh;

    // loader mapping: 128 thr -> 16 rows x 8 float4; rows lrow, lrow+16
    int lrow = tid >> 3, lcol = (tid & 7) << 2;
    // compute mapping: 4 p-rows x 2 n-cols per thread
    int pr = (tid >> 4) << 2;    // 0..28
    int nc = (tid & 15) << 1;    // 0..30
    unsigned long long acc[4] = {};

    // prolog: tail(s0) = sum of A over the s0 newest slices (s0*32 values)
    float tail;
    {
        float loc = 0.f;
        for (int k = 0; k < s0; k++) {
            int t = T_LEN - s0 * KS + lane + 32 * k;
            loc += Ab[(size_t)t * H_HEADS];
        }
#pragma unroll
        for (int off = 16; off > 0; off >>= 1)
            loc += __shfl_xor_sync(0xffffffffu, loc, off);
        tail = loc;
    }

    for (int j = s0; j < NSLICE; j += SPLIT) {
        if (tail < -THRESH) break;      // block-uniform; later items all dead
        int t0 = (NSLICE - 1 - j) * KS;

        // issue X/B tile loads first (the long pole)
        float4 xr[2], br[2];
#pragma unroll
        for (int k = 0; k < 2; k++) {
            int r = k * 16 + lrow;
            size_t base = ((size_t)b * T_LEN + t0 + r) * H_HEADS + hh;
            xr[k] = *(const float4*)(X + base * P_DIM + ph + lcol);
            br[k] = *(const float4*)(Bm + base * P_DIM + nb + lcol);
        }

        // a over slices j..j+3 (128 t, 1/lane/chunk; chunk3 = current slice)
        float a3 = Ab[(size_t)(t0 + lane) * H_HEADS];
        float aw = a3;
#pragma unroll
        for (int k = 0; k < 3; k++) {
            int t = t0 - 96 + lane + 32 * k;
            float av = (t >= 0) ? Ab[(size_t)t * H_HEADS] : 0.f;
            aw += av;
        }
        float sum4 = aw;                 // per-lane sum of 4 chunks
#pragma unroll
        for (int off = 16; off > 0; off >>= 1)
            sum4 += __shfl_xor_sync(0xffffffffu, sum4, off);   // tail increment

        // weights: inclusive prefix of a3 within warp (lane = t in slice)
        float s = a3;
#pragma unroll
        for (int off = 1; off < 32; off <<= 1) {
            float tmp = __shfl_up_sync(0xffffffffu, s, off);
            if (lane >= off) s += tmp;
        }
        float total = __shfl_sync(0xffffffffu, s, 31);
        float w = expf(tail + total - s);    // exp(tail + exclusive suffix)

        // stage (X scaled by per-row weight via shuffle)
#pragma unroll
        for (int k = 0; k < 2; k++) {
            int r = k * 16 + lrow;
            float wr = __shfl_sync(0xffffffffu, w, r & 31);
            float4 xv = xr[k];
            xv.x *= wr; xv.y *= wr; xv.z *= wr; xv.w *= wr;
            *(float4*)&sX[r][lcol] = xv;
            *(float4*)&sB[r][lcol] = br[k];
        }
        __syncthreads();                 // staging visible

#pragma unroll
        for (int tt = 0; tt < KS; tt++) {
            float4 xv = *(const float4*)&sX[tt][pr];
            unsigned long long bp = *(const unsigned long long*)&sB[tt][nc];
            acc[0] = fma2(pack2(xv.x), bp, acc[0]);
            acc[1] = fma2(pack2(xv.y), bp, acc[1]);
            acc[2] = fma2(pack2(xv.z), bp, acc[2]);
            acc[3] = fma2(pack2(xv.w), bp, acc[3]);
        }
        __syncthreads();                 // compute done before next staging
        tail += sum4;
    }

    // write this block's partial to its private scratch slot
    float* slot = g_part + (size_t)blk * (QP * QN);
#pragma unroll
    for (int i = 0; i < 4; i++) {
        float v0, v1;
        asm("mov.b64 {%0, %1}, %2;" : "=f"(v0), "=f"(v1) : "l"(acc[i]));
        *(float2*)&slot[(pr + i) * QN + nc] = make_float2(v0, v1);
    }
    __threadfence();                     // partials visible before ticket
    if (tid == 0) s_tick = atomicAdd(&g_cnt[g], 1u);
    __syncthreads();

    if (s_tick == SPLIT - 1) {
        // last-arriving block: combine the group's partials, store output
        const float* base = g_part + (size_t)(g * SPLIT) * (QP * QN);
        float* ob = out + (size_t)bh * (P_DIM * N_DIM);
#pragma unroll
        for (int i = 0; i < 4; i++) {
            float2 r = make_float2(0.f, 0.f);
#pragma unroll
            for (int sidx = 0; sidx < SPLIT; sidx++) {
                float2 v = *(const float2*)&base[sidx * (QP * QN) + (pr + i) * QN + nc];
                r.x += v.x; r.y += v.y;
            }
            *(float2*)&ob[(ph + pr + i) * N_DIM + nb + nc] = r;
        }
        if (tid == 0) g_cnt[g] = 0;      // reset for next launch / graph replay
    }
}

// ---------------------------------------------------------------------------
extern "C" void kernel_launch(void* const* d_in, const int* in_sizes, int n_in,
                              void* d_out, int out_size) {
    const float* X = (const float*)d_in[0];
    const float* A = (const float*)d_in[1];
    const float* B = (const float*)d_in[2];
    float* out = (float*)d_out;

    state_kernel<<<NGROUP * SPLIT, 128>>>(X, B, A, out);
}

// round 15
// speedup vs baseline: 1.1875x; 1.1875x over previous
#include <cuda_runtime.h>

// Problem constants (fixed by setup_inputs)
#define T_LEN 8192
#define H_HEADS 16
#define B_BATCH 2
#define P_DIM 64
#define N_DIM 64
#define BH (B_BATCH * H_HEADS)   // 32

#define KS 32                    // timesteps per slice = per work item
#define NSLICE (T_LEN / KS)      // 256
#define PHALF 32                 // p-split: block owns 32 of 64 p-rows
#define GPS 4                    // state blocks per (bh, p-half), grid-stride
#define WIN_T 256                // prep window (t-steps) = 8 slices
#define NWIN (T_LEN / WIN_T)     // 32
// exp(-10) ~ 4.5e-5: dropped tail perturbs result ~4e-5 relative; gate is 1e-3.
#define THRESH 10.0f

// Scratch (allocation-free rule: device globals)
__device__ float g_tail[BH * NSLICE];   // suffix sum of A beyond each slice (live region)
__device__ int   g_jcnt[BH];            // number of active slices per bh

// ---- packed fp32x2 helpers (sm_100+; PTX-only) ----
__device__ __forceinline__ unsigned long long fma2(unsigned long long a,
                                                   unsigned long long b,
                                                   unsigned long long c) {
    unsigned long long d;
    asm("fma.rn.f32x2 %0, %1, %2, %3;" : "=l"(d) : "l"(a), "l"(b), "l"(c));
    return d;
}
__device__ __forceinline__ unsigned long long pack2(float x) {
    unsigned long long d;
    asm("mov.b64 %0, {%1, %1};" : "=l"(d) : "f"(x));
    return d;
}

// ---------------------------------------------------------------------------
// Prep: per bh, scan A backwards in 256-t windows; write per-slice tails;
// stop once running tail < -THRESH (a<=0 => tails monotone). Publishes
// jcnt = number of active slices. Zeroes this bh's output tile.
// ---------------------------------------------------------------------------
__global__ void __launch_bounds__(256)
prep_kernel(const float* __restrict__ A, float* __restrict__ out) {
    int bh = blockIdx.x;
    int b = bh / H_HEADS, hh = bh % H_HEADS;
    int tid = threadIdx.x;
    int lane = tid & 31, wid = tid >> 5;

    __shared__ float s_chunk[8];

    float4* ob4 = (float4*)(out + (size_t)bh * (P_DIM * N_DIM));
#pragma unroll
    for (int i = 0; i < (P_DIM * N_DIM) / (256 * 4); i++)
        ob4[tid + i * 256] = make_float4(0.f, 0.f, 0.f, 0.f);

    const float* Ab = A + (size_t)b * T_LEN * H_HEADS + hh;
    float running = 0.f;
    int scut = NSLICE;
    float a_cur = Ab[(size_t)((NWIN - 1) * WIN_T + tid) * H_HEADS];

    for (int win = NWIN - 1; win >= 0; win--) {
        float a_nxt = 0.f;
        if (win > 0) a_nxt = Ab[(size_t)((win - 1) * WIN_T + tid) * H_HEADS];
        float s = a_cur;
#pragma unroll
        for (int off = 16; off > 0; off >>= 1)
            s += __shfl_xor_sync(0xffffffffu, s, off);
        if (lane == 0) s_chunk[wid] = s;
        __syncthreads();

        float ch[8];
#pragma unroll
        for (int c = 0; c < 8; c++) ch[c] = s_chunk[c];
        if (tid < 8) {
            float tl = running;
#pragma unroll
            for (int c = 7; c > tid; c--) tl += ch[c];
            g_tail[bh * NSLICE + win * 8 + tid] = tl;
            unsigned m = __ballot_sync(0xffu, tl >= -THRESH) & 0xffu;
            if (m) {
                int cand = win * 8 + (__ffs(m) - 1);
                if (cand < scut) scut = cand;
            }
        }
        running += ch[0] + ch[1] + ch[2] + ch[3] + ch[4] + ch[5] + ch[6] + ch[7];
        __syncthreads();
        if (running < -THRESH) break;
        a_cur = a_nxt;
    }
    if (tid == 0) g_jcnt[bh] = NSLICE - scut;   // last tail=0 => scut<=255, jcnt>=1
}

// ---------------------------------------------------------------------------
// State: grid (GPS, BH, 2); block (j0, bh, z) handles slices j0, j0+GPS, ...
// (newest first) for a 32x64 output half-tile. All loads (jcnt/tail/A/X/B)
// issued before the exit branch to avoid chained DRAM round-trips.
// 128 threads, 4x4 tile (f32x2), one red.v4-epilogue per block.
// ---------------------------------------------------------------------------
__global__ void __launch_bounds__(128)
state_kernel(const float* __restrict__ X, const float* __restrict__ Bm,
             const float* __restrict__ A, float* __restrict__ out) {
    int bh = blockIdx.y;
    int ph = blockIdx.z * PHALF;
    int tid = threadIdx.x;
    int b = bh / H_HEADS, hh = bh % H_HEADS;

    __shared__ float s_wt[KS];
    __shared__ float sX[KS][PHALF];
    __shared__ float sB[KS][N_DIM];

    // loader mappings
    int lrowB = tid >> 4, lcolB = (tid & 15) << 2;   // B: 8 rows x 16 f4, x4
    int lrowX = tid >> 3, lcolX = (tid & 7) << 2;    // X: 16 rows x 8 f4, x2
    // compute tile
    int p0 = (tid >> 4) << 2;   // 0..28
    int n0 = (tid & 15) << 2;   // 0..60
    unsigned long long acc[4][2] = {};
    bool any = false;

    int jcnt = g_jcnt[bh];   // independent of the LDGs below; all issue together

    for (int j = blockIdx.x; j < NSLICE; j += GPS) {
        int slice = NSLICE - 1 - j;
        int t0 = slice * KS;

        // --- issue ALL loads up front (speculative for dead blocks) ---
        float tail = g_tail[bh * NSLICE + slice];
        float a = 0.f;
        if (tid < KS)
            a = A[((size_t)b * T_LEN + t0 + tid) * H_HEADS + hh];
        float4 xr[2], br[4];
#pragma unroll
        for (int k = 0; k < 2; k++) {
            int r = k * 16 + lrowX;
            xr[k] = *(const float4*)(X + (((size_t)b * T_LEN + t0 + r) * H_HEADS + hh) * P_DIM
                                       + ph + lcolX);
        }
#pragma unroll
        for (int k = 0; k < 4; k++) {
            int r = k * 8 + lrowB;
            br[k] = *(const float4*)(Bm + (((size_t)b * T_LEN + t0 + r) * H_HEADS + hh) * P_DIM
                                        + lcolB);
        }

        // weights: warp 0, inclusive suffix scan of a within slice
        if (tid < KS) {
            int lane = tid;
            float s = a;
#pragma unroll
            for (int off = 1; off < 32; off <<= 1) {
                float tmp = __shfl_down_sync(0xffffffffu, s, off);
                if (lane + off < 32) s += tmp;
            }
            s_wt[tid] = expf(tail + s - a);   // exclusive suffix + tail
        }

        if (j >= jcnt) break;   // block-uniform; dead blocks exit before syncs

        __syncthreads();         // s_wt visible (and prev iter compute done)

        // stage (X scaled by weight)
#pragma unroll
        for (int k = 0; k < 2; k++) {
            int r = k * 16 + lrowX;
            float w = s_wt[r];
            float4 xv = xr[k];
            xv.x *= w; xv.y *= w; xv.z *= w; xv.w *= w;
            *(float4*)&sX[r][lcolX] = xv;
        }
#pragma unroll
        for (int k = 0; k < 4; k++)
            *(float4*)&sB[k * 8 + lrowB][lcolB] = br[k];
        __syncthreads();         // staging visible

#pragma unroll
        for (int tt = 0; tt < KS; tt++) {
            float4 xv = *(const float4*)&sX[tt][p0];
            ulonglong2 bp = *(const ulonglong2*)&sB[tt][n0];
            unsigned long long bv[2] = {bp.x, bp.y};
            float xs[4] = {xv.x, xv.y, xv.z, xv.w};
#pragma unroll
            for (int i = 0; i < 4; i++) {
                unsigned long long x2 = pack2(xs[i]);
#pragma unroll
                for (int jj = 0; jj < 2; jj++)
                    acc[i][jj] = fma2(x2, bv[jj], acc[i][jj]);
            }
        }
        any = true;
    }

    if (!any) return;

    // single epilogue: one red.v4 per owned output row
    float* ob = out + (size_t)bh * (P_DIM * N_DIM);
#pragma unroll
    for (int i = 0; i < 4; i++) {
        float v[4];
#pragma unroll
        for (int jj = 0; jj < 2; jj++)
            asm("mov.b64 {%0, %1}, %2;" : "=f"(v[2 * jj]), "=f"(v[2 * jj + 1])
                                        : "l"(acc[i][jj]));
        float* p = &ob[(ph + p0 + i) * N_DIM + n0];
        asm volatile("red.global.add.v4.f32 [%0], {%1, %2, %3, %4};"
                     :: "l"(p), "f"(v[0]), "f"(v[1]), "f"(v[2]), "f"(v[3]) : "memory");
    }
}

// ---------------------------------------------------------------------------
extern "C" void kernel_launch(void* const* d_in, const int* in_sizes, int n_in,
                              void* d_out, int out_size) {
    const float* X = (const float*)d_in[0];
    const float* A = (const float*)d_in[1];
    const float* B = (const float*)d_in[2];
    float* out = (float*)d_out;

    prep_kernel<<<BH, 256>>>(A, out);
    dim3 gS(GPS, BH, 2);
    state_kernel<<<gS, 128>>>(X, B, A, out);
}